// round 2
// baseline (speedup 1.0000x reference)
#include <cuda_runtime.h>
#include <cstdint>

#define MDIM 8192
#define KDIM 4096
#define NDIM 4096

#define TILE_M 128
#define TILE_N 256
#define TILE_K 64
#define NK_ITERS (KDIM / TILE_K)   // 64
#define NSTAGES 4
#define THREADS 512

// int8 scratch (device globals = allowed scratch)
__device__ int8_t g_xq[(size_t)MDIM * KDIM];
__device__ int8_t g_wq[(size_t)NDIM * KDIM];

// ---------------- helpers ----------------
__device__ __forceinline__ uint32_t smem_u32(const void* p) {
    uint32_t a;
    asm("{ .reg .u64 t; cvta.to.shared.u64 t, %1; cvt.u32.u64 %0, t; }" : "=r"(a) : "l"(p));
    return a;
}
__device__ __forceinline__ void cp_async16(uint32_t s, const void* g) {
    asm volatile("cp.async.cg.shared.global [%0], [%1], 16;" :: "r"(s), "l"(g));
}
__device__ __forceinline__ void cp_commit() { asm volatile("cp.async.commit_group;"); }
template <int N> __device__ __forceinline__ void cp_wait() {
    asm volatile("cp.async.wait_group %0;" :: "n"(N));
}
__device__ __forceinline__ void ldm_x4(uint32_t* r, uint32_t addr) {
    asm volatile("ldmatrix.sync.aligned.m8n8.x4.shared.b16 {%0,%1,%2,%3}, [%4];"
                 : "=r"(r[0]), "=r"(r[1]), "=r"(r[2]), "=r"(r[3]) : "r"(addr));
}
__device__ __forceinline__ void mma_s8(int* d, const uint32_t* a, const uint32_t* b) {
    asm volatile(
        "mma.sync.aligned.m16n8k32.row.col.s32.s8.s8.s32 "
        "{%0,%1,%2,%3}, {%4,%5,%6,%7}, {%8,%9}, {%0,%1,%2,%3};"
        : "+r"(d[0]), "+r"(d[1]), "+r"(d[2]), "+r"(d[3])
        : "r"(a[0]), "r"(a[1]), "r"(a[2]), "r"(a[3]), "r"(b[0]), "r"(b[1]));
}

// ---------------- quantize x -> int8 ----------------
__global__ void __launch_bounds__(256) quant_kernel(const float* __restrict__ x,
                                                    const float* __restrict__ is_p,
                                                    const int* __restrict__ izp_p) {
    int idx = (blockIdx.x * 256 + threadIdx.x) * 4;
    float inv = 1.0f / is_p[0];
    float zp = (float)izp_p[0];
    float4 v = *(const float4*)(x + idx);
    int q0 = (int)(fminf(fmaxf(rintf(v.x * inv) + zp, -128.f), 127.f) - zp);
    int q1 = (int)(fminf(fmaxf(rintf(v.y * inv) + zp, -128.f), 127.f) - zp);
    int q2 = (int)(fminf(fmaxf(rintf(v.z * inv) + zp, -128.f), 127.f) - zp);
    int q3 = (int)(fminf(fmaxf(rintf(v.w * inv) + zp, -128.f), 127.f) - zp);
    uint32_t packed = (uint32_t)(q0 & 255) | ((uint32_t)(q1 & 255) << 8) |
                      ((uint32_t)(q2 & 255) << 16) | ((uint32_t)(q3 & 255) << 24);
    *reinterpret_cast<uint32_t*>(g_xq + idx) = packed;
}

// ---------------- weight int32 -> int8 ----------------
__global__ void __launch_bounds__(256) wconv_kernel(const int* __restrict__ w,
                                                    const int* __restrict__ wzp) {
    int n = blockIdx.y;
    int k = (blockIdx.x * 256 + threadIdx.x) * 4;
    int zp = wzp[n];
    size_t base = (size_t)n * KDIM + k;
    int4 v = *(const int4*)(w + base);
    uint32_t packed = (uint32_t)((v.x - zp) & 255) | ((uint32_t)((v.y - zp) & 255) << 8) |
                      ((uint32_t)((v.z - zp) & 255) << 16) | ((uint32_t)((v.w - zp) & 255) << 24);
    *reinterpret_cast<uint32_t*>(g_wq + base) = packed;
}

// ---------------- IMMA GEMM ----------------
// smem: alpha[256] f32 @0, beta[256] f32 @1024, stages @2048
// stage: A 128 rows x 80B (10240) + B 256 rows x 80B (20480) = 30720
#define STRIDE_ROW 80
#define S_AB 2048
#define STAGE_BYTES 30720
#define SMEM_BYTES (S_AB + NSTAGES * STAGE_BYTES)   // 124928

__device__ __forceinline__ void load_stage(uint32_t sbase, int stage,
                                           const int8_t* gA, const int8_t* gB,
                                           int k0, int tid) {
    uint32_t sA = sbase + S_AB + stage * STAGE_BYTES;
    uint32_t sB = sA + 10240;
    {   // A: 128 rows x 4 chunks = 512
        int row = tid >> 2, ch = tid & 3;
        cp_async16(sA + row * STRIDE_ROW + ch * 16,
                   gA + (size_t)row * KDIM + k0 + ch * 16);
    }
#pragma unroll
    for (int i = 0; i < 2; i++) {  // B: 256 rows x 4 chunks = 1024
        int idx = tid + THREADS * i;
        int row = idx >> 2, ch = idx & 3;
        cp_async16(sB + row * STRIDE_ROW + ch * 16,
                   gB + (size_t)row * KDIM + k0 + ch * 16);
    }
}

__global__ void __launch_bounds__(THREADS, 1)
gemm_kernel(const float* __restrict__ wscale, const float* __restrict__ in_scale,
            const int* __restrict__ bias_int, const float* __restrict__ bias_scale,
            float* __restrict__ out) {
    extern __shared__ __align__(1024) char smem[];
    const uint32_t sbase = smem_u32(smem);
    const int tid = threadIdx.x;
    const int lane = tid & 31;
    const int wid = tid >> 5;
    const int warpM = wid & 3;        // 4 -> 32 rows each
    const int warpN = wid >> 2;       // 4 -> 64 cols each

    // raster: groups of 8 m-tiles x 16 n-tiles (keeps B L2-resident)
    const int tiles_n = NDIM / TILE_N;              // 16
    const int per_group = 8 * tiles_n;              // 128
    int g = blockIdx.x / per_group;
    int r0 = blockIdx.x % per_group;
    int mt = g * 8 + (r0 & 7);
    int nt = r0 >> 3;
    const int m0 = mt * TILE_M;
    const int n0 = nt * TILE_N;

    float* alpha_s = (float*)smem;
    float* beta_s = (float*)(smem + 1024);
    if (tid < 256) {
        int n = n0 + tid;
        alpha_s[tid] = in_scale[0] * wscale[n];
        beta_s[tid] = (float)bias_int[n] * bias_scale[n];
    }

    const int8_t* gA = g_xq + (size_t)m0 * KDIM;
    const int8_t* gB = g_wq + (size_t)n0 * KDIM;

    // prologue: stages 0..2
    load_stage(sbase, 0, gA, gB, 0, tid); cp_commit();
    load_stage(sbase, 1, gA, gB, TILE_K, tid); cp_commit();
    load_stage(sbase, 2, gA, gB, 2 * TILE_K, tid); cp_commit();

    int acc[2][8][4];
#pragma unroll
    for (int i = 0; i < 2; i++)
#pragma unroll
        for (int j = 0; j < 8; j++)
#pragma unroll
            for (int q = 0; q < 4; q++) acc[i][j][q] = 0;

    // ldmatrix lane-address components
    const int a_row = lane & 15;            // rows 0-15
    const int a_kh = (lane >> 4) & 1;       // k half (16B)
    const int b_noff = (lane & 7) + ((lane & 16) >> 1);   // 0-15
    const int b_kh = (lane >> 3) & 1;

#pragma unroll 1
    for (int it = 0; it < NK_ITERS; it++) {
        cp_wait<NSTAGES - 2>();
        __syncthreads();

        if (it + 3 < NK_ITERS) {
            load_stage(sbase, (it + 3) & (NSTAGES - 1), gA, gB, (it + 3) * TILE_K, tid);
            cp_commit();
        } else {
            cp_commit();   // empty group keeps wait_group semantics uniform
        }

        uint32_t sA = sbase + S_AB + (it & (NSTAGES - 1)) * STAGE_BYTES;
        uint32_t sB = sA + 10240;

#pragma unroll
        for (int ks = 0; ks < 2; ks++) {   // two k=32 steps
            uint32_t a[2][4], b[4][4];
#pragma unroll
            for (int mi = 0; mi < 2; mi++)
                ldm_x4(a[mi], sA + (warpM * 32 + mi * 16 + a_row) * STRIDE_ROW +
                                  ks * 32 + a_kh * 16);
#pragma unroll
            for (int np = 0; np < 4; np++)
                ldm_x4(b[np], sB + (warpN * 64 + np * 16 + b_noff) * STRIDE_ROW +
                                  ks * 32 + b_kh * 16);
#pragma unroll
            for (int mi = 0; mi < 2; mi++)
#pragma unroll
                for (int ni = 0; ni < 8; ni++)
                    mma_s8(acc[mi][ni], a[mi], &b[ni >> 1][(ni & 1) * 2]);
        }
    }

    // epilogue: dequant + bias, direct stores
    const int gid = lane >> 2, tig = lane & 3;
#pragma unroll
    for (int mi = 0; mi < 2; mi++) {
#pragma unroll
        for (int ni = 0; ni < 8; ni++) {
            int nloc = warpN * 64 + ni * 8 + tig * 2;
            float al0 = alpha_s[nloc], al1 = alpha_s[nloc + 1];
            float be0 = beta_s[nloc], be1 = beta_s[nloc + 1];
            size_t r = (size_t)m0 + warpM * 32 + mi * 16 + gid;
            float2 v0 = {(float)acc[mi][ni][0] * al0 + be0,
                         (float)acc[mi][ni][1] * al1 + be1};
            float2 v1 = {(float)acc[mi][ni][2] * al0 + be0,
                         (float)acc[mi][ni][3] * al1 + be1};
            *reinterpret_cast<float2*>(out + r * NDIM + n0 + nloc) = v0;
            *reinterpret_cast<float2*>(out + (r + 8) * NDIM + n0 + nloc) = v1;
        }
    }
}

// ---------------- launch ----------------
extern "C" void kernel_launch(void* const* d_in, const int* in_sizes, int n_in,
                              void* d_out, int out_size) {
    const float* x = (const float*)d_in[0];
    const int* w = (const int*)d_in[1];
    const float* wsc = (const float*)d_in[2];
    const int* wzp = (const int*)d_in[3];
    const float* isc = (const float*)d_in[4];
    const int* izp = (const int*)d_in[5];
    const int* bi = (const int*)d_in[6];
    const float* bsc = (const float*)d_in[7];
    float* out = (float*)d_out;

    cudaFuncSetAttribute(gemm_kernel, cudaFuncAttributeMaxDynamicSharedMemorySize,
                         SMEM_BYTES);

    quant_kernel<<<(MDIM * KDIM) / 1024, 256>>>(x, isc, izp);
    wconv_kernel<<<dim3(KDIM / 1024, NDIM), 256>>>(w, wzp);
    gemm_kernel<<<(MDIM / TILE_M) * (NDIM / TILE_N), THREADS, SMEM_BYTES>>>(
        wsc, isc, bi, bsc, out);
}

// round 3
// speedup vs baseline: 2.5225x; 2.5225x over previous
#include <cuda_runtime.h>
#include <cuda_bf16.h>
#include <cstdint>

#define MDIM 8192
#define KDIM 4096
#define NDIM 4096

#define TILE_M 128
#define TILE_N 256
#define TILE_K 64
#define NK_ITERS (KDIM / TILE_K)   // 64
#define NSTAGES 3
#define THREADS 512

// bf16 scratch (device globals = allowed scratch)
__device__ __nv_bfloat16 g_xq[(size_t)MDIM * KDIM];
__device__ __nv_bfloat16 g_wq[(size_t)NDIM * KDIM];

// ---------------- helpers ----------------
__device__ __forceinline__ uint32_t smem_u32(const void* p) {
    uint32_t a;
    asm("{ .reg .u64 t; cvta.to.shared.u64 t, %1; cvt.u32.u64 %0, t; }" : "=r"(a) : "l"(p));
    return a;
}
__device__ __forceinline__ void cp_async16(uint32_t s, const void* g) {
    asm volatile("cp.async.cg.shared.global [%0], [%1], 16;" :: "r"(s), "l"(g));
}
__device__ __forceinline__ void cp_commit() { asm volatile("cp.async.commit_group;"); }
template <int N> __device__ __forceinline__ void cp_wait() {
    asm volatile("cp.async.wait_group %0;" :: "n"(N));
}
__device__ __forceinline__ void ldm_x4(uint32_t* r, uint32_t addr) {
    asm volatile("ldmatrix.sync.aligned.m8n8.x4.shared.b16 {%0,%1,%2,%3}, [%4];"
                 : "=r"(r[0]), "=r"(r[1]), "=r"(r[2]), "=r"(r[3]) : "r"(addr));
}
__device__ __forceinline__ void mma_bf16(float* d, const uint32_t* a, const uint32_t* b) {
    asm volatile(
        "mma.sync.aligned.m16n8k16.row.col.f32.bf16.bf16.f32 "
        "{%0,%1,%2,%3}, {%4,%5,%6,%7}, {%8,%9}, {%0,%1,%2,%3};"
        : "+f"(d[0]), "+f"(d[1]), "+f"(d[2]), "+f"(d[3])
        : "r"(a[0]), "r"(a[1]), "r"(a[2]), "r"(a[3]), "r"(b[0]), "r"(b[1]));
}
__device__ __forceinline__ uint32_t pack_bf16(float a, float b) {
    __nv_bfloat162 t = __floats2bfloat162_rn(a, b);
    return *reinterpret_cast<uint32_t*>(&t);
}

// ---------------- quantize x -> bf16(int) ----------------
__global__ void __launch_bounds__(256) quant_kernel(const float* __restrict__ x,
                                                    const float* __restrict__ is_p,
                                                    const int* __restrict__ izp_p) {
    int idx = (blockIdx.x * 256 + threadIdx.x) * 4;
    float inv = 1.0f / is_p[0];
    float zp = (float)izp_p[0];
    float4 v = *(const float4*)(x + idx);
    float q0 = fminf(fmaxf(rintf(v.x * inv) + zp, -128.f), 127.f) - zp;
    float q1 = fminf(fmaxf(rintf(v.y * inv) + zp, -128.f), 127.f) - zp;
    float q2 = fminf(fmaxf(rintf(v.z * inv) + zp, -128.f), 127.f) - zp;
    float q3 = fminf(fmaxf(rintf(v.w * inv) + zp, -128.f), 127.f) - zp;
    uint2 o;
    o.x = pack_bf16(q0, q1);
    o.y = pack_bf16(q2, q3);
    *reinterpret_cast<uint2*>(g_xq + idx) = o;
}

// ---------------- weight int32 -> bf16 ----------------
__global__ void __launch_bounds__(256) wconv_kernel(const int* __restrict__ w,
                                                    const int* __restrict__ wzp) {
    int n = blockIdx.y;
    int k = (blockIdx.x * 256 + threadIdx.x) * 4;
    int zp = wzp[n];
    size_t base = (size_t)n * KDIM + k;
    int4 v = *(const int4*)(w + base);
    uint2 o;
    o.x = pack_bf16((float)(v.x - zp), (float)(v.y - zp));
    o.y = pack_bf16((float)(v.z - zp), (float)(v.w - zp));
    *reinterpret_cast<uint2*>(g_wq + base) = o;
}

// ---------------- HMMA bf16 GEMM ----------------
// smem: alpha[256] f32 @0, beta[256] f32 @1024, stages @2048
// stage: A 128 rows x 144B (18432) + B 256 rows x 144B (36864) = 55296
#define STRIDE_ROW 144
#define S_AB 2048
#define A_BYTES 18432
#define STAGE_BYTES 55296
#define SMEM_BYTES (S_AB + NSTAGES * STAGE_BYTES)   // 167936

__device__ __forceinline__ void load_stage(uint32_t sbase, int stage,
                                           const __nv_bfloat16* gA,
                                           const __nv_bfloat16* gB,
                                           int k0, int tid) {
    uint32_t sA = sbase + S_AB + stage * STAGE_BYTES;
    uint32_t sB = sA + A_BYTES;
#pragma unroll
    for (int i = 0; i < 2; i++) {   // A: 128 rows x 8 chunks(16B) = 1024
        int idx = tid + THREADS * i;
        int row = idx >> 3, ch = idx & 7;
        cp_async16(sA + row * STRIDE_ROW + ch * 16,
                   gA + (size_t)row * KDIM + k0 + ch * 8);
    }
#pragma unroll
    for (int i = 0; i < 4; i++) {   // B: 256 rows x 8 chunks = 2048
        int idx = tid + THREADS * i;
        int row = idx >> 3, ch = idx & 7;
        cp_async16(sB + row * STRIDE_ROW + ch * 16,
                   gB + (size_t)row * KDIM + k0 + ch * 8);
    }
}

__global__ void __launch_bounds__(THREADS, 1)
gemm_kernel(const float* __restrict__ wscale, const float* __restrict__ in_scale,
            const int* __restrict__ bias_int, const float* __restrict__ bias_scale,
            float* __restrict__ out) {
    extern __shared__ __align__(1024) char smem[];
    const uint32_t sbase = smem_u32(smem);
    const int tid = threadIdx.x;
    const int lane = tid & 31;
    const int wid = tid >> 5;
    const int warpM = wid & 3;        // 4 -> 32 rows each
    const int warpN = wid >> 2;       // 4 -> 64 cols each

    // raster: groups of 8 m-tiles x 16 n-tiles (keeps B L2-resident)
    const int tiles_n = NDIM / TILE_N;              // 16
    const int per_group = 8 * tiles_n;              // 128
    int g = blockIdx.x / per_group;
    int r0 = blockIdx.x % per_group;
    int mt = g * 8 + (r0 & 7);
    int nt = r0 >> 3;
    const int m0 = mt * TILE_M;
    const int n0 = nt * TILE_N;

    float* alpha_s = (float*)smem;
    float* beta_s = (float*)(smem + 1024);
    if (tid < 256) {
        int n = n0 + tid;
        alpha_s[tid] = in_scale[0] * wscale[n];
        beta_s[tid] = (float)bias_int[n] * bias_scale[n];
    }

    const __nv_bfloat16* gA = g_xq + (size_t)m0 * KDIM;
    const __nv_bfloat16* gB = g_wq + (size_t)n0 * KDIM;

    // prologue: stages 0,1
    load_stage(sbase, 0, gA, gB, 0, tid); cp_commit();
    load_stage(sbase, 1, gA, gB, TILE_K, tid); cp_commit();

    float acc[2][8][4];
#pragma unroll
    for (int i = 0; i < 2; i++)
#pragma unroll
        for (int j = 0; j < 8; j++)
#pragma unroll
            for (int q = 0; q < 4; q++) acc[i][j][q] = 0.0f;

    // ldmatrix lane-address components (same mapping proven in int8 round)
    const int a_row = lane & 15;                       // m rows 0-15
    const int a_kh = (lane >> 4) & 1;                  // +16B k-half
    const int b_noff = (lane & 7) + ((lane & 16) >> 1); // n rows 0-15
    const int b_kh = (lane >> 3) & 1;                  // +16B k-half

    int stage_ld = 2 % NSTAGES;

#pragma unroll 1
    for (int it = 0; it < NK_ITERS; it++) {
        cp_wait<NSTAGES - 2>();
        __syncthreads();

        if (it + 2 < NK_ITERS) {
            load_stage(sbase, stage_ld, gA, gB, (it + 2) * TILE_K, tid);
            cp_commit();
        } else {
            cp_commit();
        }
        stage_ld++; if (stage_ld == NSTAGES) stage_ld = 0;

        int stage = it % NSTAGES;
        uint32_t sA = sbase + S_AB + stage * STAGE_BYTES;
        uint32_t sB = sA + A_BYTES;

#pragma unroll
        for (int ks = 0; ks < 4; ks++) {   // four k=16 steps
            uint32_t a[2][4], b[4][4];
#pragma unroll
            for (int mi = 0; mi < 2; mi++)
                ldm_x4(a[mi], sA + (warpM * 32 + mi * 16 + a_row) * STRIDE_ROW +
                                  ks * 32 + a_kh * 16);
#pragma unroll
            for (int np = 0; np < 4; np++)
                ldm_x4(b[np], sB + (warpN * 64 + np * 16 + b_noff) * STRIDE_ROW +
                                  ks * 32 + b_kh * 16);
#pragma unroll
            for (int mi = 0; mi < 2; mi++)
#pragma unroll
                for (int ni = 0; ni < 8; ni++)
                    mma_bf16(acc[mi][ni], a[mi], &b[ni >> 1][(ni & 1) * 2]);
        }
    }

    // epilogue: dequant + bias, direct stores
    const int gid = lane >> 2, tig = lane & 3;
#pragma unroll
    for (int mi = 0; mi < 2; mi++) {
#pragma unroll
        for (int ni = 0; ni < 8; ni++) {
            int nloc = warpN * 64 + ni * 8 + tig * 2;
            float al0 = alpha_s[nloc], al1 = alpha_s[nloc + 1];
            float be0 = beta_s[nloc], be1 = beta_s[nloc + 1];
            size_t r = (size_t)m0 + warpM * 32 + mi * 16 + gid;
            float2 v0 = {acc[mi][ni][0] * al0 + be0, acc[mi][ni][1] * al1 + be1};
            float2 v1 = {acc[mi][ni][2] * al0 + be0, acc[mi][ni][3] * al1 + be1};
            *reinterpret_cast<float2*>(out + r * NDIM + n0 + nloc) = v0;
            *reinterpret_cast<float2*>(out + (r + 8) * NDIM + n0 + nloc) = v1;
        }
    }
}

// ---------------- launch ----------------
extern "C" void kernel_launch(void* const* d_in, const int* in_sizes, int n_in,
                              void* d_out, int out_size) {
    const float* x = (const float*)d_in[0];
    const int* w = (const int*)d_in[1];
    const float* wsc = (const float*)d_in[2];
    const int* wzp = (const int*)d_in[3];
    const float* isc = (const float*)d_in[4];
    const int* izp = (const int*)d_in[5];
    const int* bi = (const int*)d_in[6];
    const float* bsc = (const float*)d_in[7];
    float* out = (float*)d_out;

    cudaFuncSetAttribute(gemm_kernel, cudaFuncAttributeMaxDynamicSharedMemorySize,
                         SMEM_BYTES);

    quant_kernel<<<(MDIM * KDIM) / 1024, 256>>>(x, isc, izp);
    wconv_kernel<<<dim3(KDIM / 1024, NDIM), 256>>>(w, wzp);
    gemm_kernel<<<(MDIM / TILE_M) * (NDIM / TILE_N), THREADS, SMEM_BYTES>>>(
        wsc, isc, bi, bsc, out);
}